// round 10
// baseline (speedup 1.0000x reference)
#include <cuda_runtime.h>
#include <cuda_bf16.h>
#include <float.h>

#define Bn 128
#define On 1024
#define In 1024
#define EPSc 1e-7f
#define L2E 1.4426950408889634f
#define CUT_NATS 20.794415417f   // 30*ln2: drop softmax terms with weight < 2^-30
#define W 8                      // warps (=i's) per kmega block
#define LISTMAX 448              // per-warp candidate capacity (dense fallback beyond)

// Scratch (no allocs allowed)
__device__ float g_c2_im[In * On];    // C^2, i-major [i][o]
__device__ float g_data_im[In * Bn];  // data transposed [i][b]

__device__ __forceinline__ float rsq(float x) {
    float r;
    asm("rsqrt.approx.ftz.f32 %0, %1;" : "=f"(r) : "f"(x));
    return r;
}
__device__ __forceinline__ float ex2(float x) {
    float r;
    asm("ex2.approx.ftz.f32 %0, %1;" : "=f"(r) : "f"(x));
    return r;
}

// ---------------- Kernel P: C^2 transpose + data transpose ----------------
// blocks 0..1023: C^2 tiles (keeps IEEE div.rn — C is cancellation-amplified).
// blocks 1024..1151: data [128,1024] -> data_im [1024,128].
__global__ void kprep(const float* __restrict__ data,
                      const float* __restrict__ ix, const float* __restrict__ iy,
                      const float* __restrict__ ox, const float* __restrict__ oy,
                      const float* __restrict__ la, const float* __restrict__ lm) {
    __shared__ float tile[32][33];
    int tx = threadIdx.x & 31;
    int ty = threadIdx.x >> 5;

    if (blockIdx.x < 1024) {
        int ob  = (blockIdx.x & 31) * 32;   // o tile base
        int ibt = (blockIdx.x >> 5) * 32;   // i tile base
#pragma unroll
        for (int k = 0; k < 4; k++) {
            int o = ob + ty + k * 8;
            int idx = o * In + ibt + tx;    // coalesced over tx
            float c = (ix[idx] / iy[idx] + la[idx]) * (1.0f + lm[idx]) - ox[idx] / oy[idx];
            tile[ty + k * 8][tx] = c * c;
        }
        __syncthreads();
#pragma unroll
        for (int k = 0; k < 4; k++) {
            int il = ty + k * 8;
            g_c2_im[(ibt + il) * In + ob + tx] = tile[tx][il];
        }
    } else {
        int tb = blockIdx.x - 1024;         // 0..127
        int bb = (tb & 3) * 32;             // b tile base
        int ib = (tb >> 2) * 32;            // i tile base
#pragma unroll
        for (int k = 0; k < 4; k++) {
            int b = bb + ty + k * 8;
            tile[ty + k * 8][tx] = data[b * In + ib + tx];
        }
        __syncthreads();
#pragma unroll
        for (int k = 0; k < 4; k++) {
            int il = ty + k * 8;
            g_data_im[(ib + il) * Bn + bb + tx] = tile[tx][il];
        }
    }
}

// ---------------- Kernel M: warp-per-i sparse softmax, no block barriers ----------------
__global__ void __launch_bounds__(256) kmega(float* __restrict__ out) {
    __shared__ int   s_o[W][LISTMAX];
    __shared__ float s_c2[W][LISTMAX];
    __shared__ int   s_cnt[W];

    int t = threadIdx.x, lane = t & 31, warp = t >> 5;
    int i = blockIdx.x * W + warp;          // grid = In/W = 128 -> single wave

    // --- row C^2[:,i] into registers (32 floats/lane) ---
    const float4* src = (const float4*)(g_c2_im + (size_t)i * In);
    float4 c[8];
#pragma unroll
    for (int j = 0; j < 8; j++) c[j] = src[lane + 32 * j];

    // --- warp min -> c2min ---
    float mn = FLT_MAX;
#pragma unroll
    for (int j = 0; j < 8; j++)
        mn = fminf(mn, fminf(fminf(c[j].x, c[j].y), fminf(c[j].z, c[j].w)));
#pragma unroll
    for (int s = 16; s; s >>= 1) mn = fminf(mn, __shfl_xor_sync(0xffffffffu, mn, s));
    float c2min = mn;

    // --- per-b scalars (lane handles b = lane + 32r) + keep threshold ---
    const float* dcol = g_data_im + (size_t)i * Bn;
    float dd[4], g2[4], Bm[4];
    float kmax = 0.f;
#pragma unroll
    for (int r = 0; r < 4; r++) {
        dd[r] = dcol[lane + 32 * r];        // coalesced
        float g = 1.0f / (1.0f + __expf(-dd[r]));
        g2[r] = g * g;
        float smax = rsq(fmaf(c2min, g2[r], EPSc));
        Bm[r] = -smax * L2E;
        float q = smax - CUT_NATS;
        float keep = (q > 0.f) ? (1.0f / (q * q) - EPSc) / g2[r] : FLT_MAX;
        kmax = fmaxf(kmax, keep);
    }
#pragma unroll
    for (int s = 16; s; s >>= 1) kmax = fmaxf(kmax, __shfl_xor_sync(0xffffffffu, kmax, s));
    float T = kmax;

    // --- compact candidates {o : C^2 <= T} as (o, c2) pairs ---
    if (lane == 0) s_cnt[warp] = 0;
    __syncwarp();
#pragma unroll
    for (int j = 0; j < 8; j++) {
        int obase = 4 * (lane + 32 * j);
        float v;
        int p;
        v = c[j].x; if (v <= T) { p = atomicAdd(&s_cnt[warp], 1); if (p < LISTMAX) { s_o[warp][p] = obase;     s_c2[warp][p] = v; } }
        v = c[j].y; if (v <= T) { p = atomicAdd(&s_cnt[warp], 1); if (p < LISTMAX) { s_o[warp][p] = obase + 1; s_c2[warp][p] = v; } }
        v = c[j].z; if (v <= T) { p = atomicAdd(&s_cnt[warp], 1); if (p < LISTMAX) { s_o[warp][p] = obase + 2; s_c2[warp][p] = v; } }
        v = c[j].w; if (v <= T) { p = atomicAdd(&s_cnt[warp], 1); if (p < LISTMAX) { s_o[warp][p] = obase + 3; s_c2[warp][p] = v; } }
    }
    __syncwarp();
    int cnt = s_cnt[warp];

    float S[4] = {0.f, 0.f, 0.f, 0.f};
    if (cnt <= LISTMAX) {
        // --- sparse path: every lane walks the shared list (full S, no reduce) ---
        for (int k = 0; k < cnt; k++) {
            float c2o = s_c2[warp][k];      // LDS broadcast
#pragma unroll
            for (int r = 0; r < 4; r++)
                S[r] += ex2(fmaf(rsq(fmaf(c2o, g2[r], EPSc)), L2E, Bm[r]));
        }
        float coef[4];
#pragma unroll
        for (int r = 0; r < 4; r++) coef[r] = __fdividef(dd[r], S[r]);
        for (int k = 0; k < cnt; k++) {
            int o = s_o[warp][k];
            float c2o = s_c2[warp][k];
#pragma unroll
            for (int r = 0; r < 4; r++) {
                float e = ex2(fmaf(rsq(fmaf(c2o, g2[r], EPSc)), L2E, Bm[r]));
                atomicAdd(&out[(size_t)(lane + 32 * r) * On + o], coef[r] * e);
            }
        }
    } else {
        // --- dense fallback (correct for any data; statistically never taken) ---
#pragma unroll
        for (int r = 0; r < 4; r++) {
            float s = 0.f;
#pragma unroll
            for (int j = 0; j < 8; j++) {
                s += ex2(fmaf(rsq(fmaf(c[j].x, g2[r], EPSc)), L2E, Bm[r]));
                s += ex2(fmaf(rsq(fmaf(c[j].y, g2[r], EPSc)), L2E, Bm[r]));
                s += ex2(fmaf(rsq(fmaf(c[j].z, g2[r], EPSc)), L2E, Bm[r]));
                s += ex2(fmaf(rsq(fmaf(c[j].w, g2[r], EPSc)), L2E, Bm[r]));
            }
#pragma unroll
            for (int sh = 16; sh; sh >>= 1) s += __shfl_xor_sync(0xffffffffu, s, sh);
            S[r] = s;
        }
        float coef[4];
#pragma unroll
        for (int r = 0; r < 4; r++) coef[r] = __fdividef(dd[r], S[r]);
#pragma unroll
        for (int j = 0; j < 8; j++) {
            int obase = 4 * (lane + 32 * j);
            const float vv[4] = {c[j].x, c[j].y, c[j].z, c[j].w};
#pragma unroll
            for (int m = 0; m < 4; m++)
#pragma unroll
                for (int r = 0; r < 4; r++) {
                    float e = ex2(fmaf(rsq(fmaf(vv[m], g2[r], EPSc)), L2E, Bm[r]));
                    atomicAdd(&out[(size_t)(lane + 32 * r) * On + obase + m], coef[r] * e);
                }
        }
    }
}

extern "C" void kernel_launch(void* const* d_in, const int* in_sizes, int n_in,
                              void* d_out, int out_size) {
    const float* data = (const float*)d_in[0];
    const float* ix   = (const float*)d_in[1];
    const float* iy   = (const float*)d_in[2];
    const float* ox   = (const float*)d_in[3];
    const float* oy   = (const float*)d_in[4];
    const float* la   = (const float*)d_in[5];
    const float* lm   = (const float*)d_in[6];
    float* out = (float*)d_out;

    cudaMemsetAsync(out, 0, (size_t)out_size * sizeof(float));
    kprep<<<1152, 256>>>(data, ix, iy, ox, oy, la, lm);
    kmega<<<In / W, 256>>>(out);
}